// round 8
// baseline (speedup 1.0000x reference)
#include <cuda_runtime.h>
#include <mma.h>
#include <math.h>
#include <stdint.h>

using namespace nvcuda;

// Problem constants
#define BATCH 2
#define SEQ 2048
#define DIM 768
#define NHEAD 12
#define HDIM 64
#define QKV_DIM (3 * DIM)     // 2304
#define M_TOTAL (BATCH * SEQ) // 4096
#define SCALE 0.125f          // 64^-0.5

// Scratch (device globals; no allocations allowed)
__device__ float g_q[BATCH * NHEAD * SEQ * HDIM];
__device__ float g_k[BATCH * NHEAD * SEQ * HDIM];
__device__ float g_v[BATCH * NHEAD * SEQ * HDIM];
__device__ float g_x[M_TOTAL * DIM];
__device__ float g_a[M_TOTAL * DIM];     // tf32-truncated inputs
__device__ float g_wq[QKV_DIM * DIM];    // tf32-truncated w_qkv
__device__ float g_wf[DIM * DIM];        // tf32-truncated w_fc
__device__ int   g_idx[BATCH * SEQ];
__device__ int   g_cnt[BATCH];

typedef wmma::fragment<wmma::matrix_a, 16, 16, 8, wmma::precision::tf32, wmma::row_major> AFrag;
typedef wmma::fragment<wmma::matrix_b, 16, 16, 8, wmma::precision::tf32, wmma::col_major> BFragCol;
typedef wmma::fragment<wmma::matrix_b, 16, 16, 8, wmma::precision::tf32, wmma::row_major> BFragRow;
typedef wmma::fragment<wmma::accumulator, 16, 16, 8, float> CFrag;

__device__ __forceinline__ float4 tf32x4(float4 v) {
    v.x = wmma::__float_to_tf32(v.x);
    v.y = wmma::__float_to_tf32(v.y);
    v.z = wmma::__float_to_tf32(v.z);
    v.w = wmma::__float_to_tf32(v.w);
    return v;
}
__device__ __forceinline__ uint32_t smem_u32(const void* p) {
    uint32_t a;
    asm("{ .reg .u64 t; cvta.to.shared.u64 t, %1; cvt.u32.u64 %0, t; }" : "=r"(a) : "l"(p));
    return a;
}
__device__ __forceinline__ void cp16(uint32_t dst, const void* src) {
    asm volatile("cp.async.cg.shared.global [%0], [%1], 16;" :: "r"(dst), "l"(src));
}
#define CP_COMMIT() asm volatile("cp.async.commit_group;" ::: "memory")
#define CP_WAIT1()  asm volatile("cp.async.wait_group 1;" ::: "memory")

// ---------------------------------------------------------------------------
// Kernel -1: elementwise tf32 truncation (rna), float4-vectorized.
// ---------------------------------------------------------------------------
__global__ void convert_kernel(const float* __restrict__ in, float* __restrict__ outp, int n4)
{
    int i = blockIdx.x * blockDim.x + threadIdx.x;
    if (i < n4) *(float4*)&outp[i * 4] = tf32x4(*(const float4*)&in[i * 4]);
}

// ---------------------------------------------------------------------------
// Kernel 0: per-batch compaction of unmasked key indices (mask <= 0).
// Masked keys get score -1e7; exp underflows to exactly 0 in fp32, so
// dropping them is numerically identical to the reference.
// ---------------------------------------------------------------------------
__global__ void compact_kernel(const int* __restrict__ mask)
{
    __shared__ int cnts[256];
    const int b = blockIdx.x;
    const int t = threadIdx.x;
    const int PER = SEQ / 256; // 8

    int m[PER];
    int local = 0;
#pragma unroll
    for (int i = 0; i < PER; i++) {
        m[i] = mask[b * SEQ + t * PER + i];
        local += (m[i] <= 0);
    }
    cnts[t] = local;
    __syncthreads();
    for (int off = 1; off < 256; off <<= 1) {
        int v = (t >= off) ? cnts[t - off] : 0;
        __syncthreads();
        cnts[t] += v;
        __syncthreads();
    }
    int w = cnts[t] - local;
#pragma unroll
    for (int i = 0; i < PER; i++)
        if (m[i] <= 0) g_idx[b * SEQ + (w++)] = t * PER + i;
    if (t == 255) g_cnt[b] = cnts[255];
}

// ---------------------------------------------------------------------------
// GEMM: C[m,d] = sum_c A[m,c] * W[d,c], inputs pre-truncated to tf32.
// 128(M) x 64(N) block tile, 4 warps (2x2), 64x32 warp tile, BK=16 floats,
// 3-stage cp.async pipeline, one __syncthreads per chunk.
// ---------------------------------------------------------------------------
#define STAGES 3
#define BKF 16
#define LDA 20
#define STAGE_F ((128 + 64) * LDA)   // 3840 floats per stage
#define W_OFF (128 * LDA)            // 2560
#define NCHUNK (DIM / BKF)           // 48

template <bool IS_QKV>
__global__ __launch_bounds__(128, 4) void tc_gemm_kernel(
    const float* __restrict__ bias, float* __restrict__ out)
{
    __shared__ float pool[STAGES * STAGE_F]; // 46080 B

    const float* Ap = IS_QKV ? g_a : g_x;
    const float* Wp = IS_QKV ? g_wq : g_wf;

    const int tid = threadIdx.x;
    const int w = tid >> 5;
    const int wy = w >> 1;      // 0..1 (m)
    const int wx = w & 1;       // 0..1 (n)
    const int m0 = blockIdx.y << 7;
    const int d0 = blockIdx.x << 6;

    const int arow = tid >> 2;          // 0..31
    const int acol4 = (tid & 3) << 2;   // 0,4,8,12
    const uint32_t smb = smem_u32(pool);

    CFrag acc[4][2];
#pragma unroll
    for (int i = 0; i < 4; i++)
#pragma unroll
        for (int j = 0; j < 2; j++) wmma::fill_fragment(acc[i][j], 0.f);

    // stage issuer: A tile 128x16 (4 cp/thread), W tile 64x16 (2 cp/thread)
    auto issue = [&](int c) {
        if (c < NCHUNK) {
            const int s = c % STAGES;
            const float* ab = Ap + (size_t)(m0 + arow) * DIM + c * BKF + acol4;
            const float* wb = Wp + (size_t)(d0 + arow) * DIM + c * BKF + acol4;
            uint32_t adst = smb + (uint32_t)(s * STAGE_F + arow * LDA + acol4) * 4;
            uint32_t wdst = adst + (uint32_t)W_OFF * 4;
#pragma unroll
            for (int i = 0; i < 4; i++)
                cp16(adst + (uint32_t)i * 32 * LDA * 4, ab + (size_t)i * 32 * DIM);
#pragma unroll
            for (int i = 0; i < 2; i++)
                cp16(wdst + (uint32_t)i * 32 * LDA * 4, wb + (size_t)i * 32 * DIM);
        }
        CP_COMMIT();
    };

    issue(0);
    issue(1);

    for (int c = 0; c < NCHUNK; c++) {
        CP_WAIT1();
        __syncthreads();
        issue(c + 2);

        const float* As_ = pool + (c % STAGES) * STAGE_F;
        const float* Ws_ = As_ + W_OFF;
#pragma unroll
        for (int ks = 0; ks < 2; ks++) {
            AFrag am[4];
            BFragCol bn[2];
#pragma unroll
            for (int ms = 0; ms < 4; ms++)
                wmma::load_matrix_sync(am[ms], &As_[(wy * 64 + ms * 16) * LDA + ks * 8], LDA);
#pragma unroll
            for (int ns = 0; ns < 2; ns++)
                wmma::load_matrix_sync(bn[ns], &Ws_[(wx * 32 + ns * 16) * LDA + ks * 8], LDA);
#pragma unroll
            for (int ms = 0; ms < 4; ms++)
#pragma unroll
                for (int ns = 0; ns < 2; ns++)
                    wmma::mma_sync(acc[ms][ns], am[ms], bn[ns], acc[ms][ns]);
        }
    }
    __syncthreads();

    if (IS_QKV) {
        // Scatter epilogue into [b,h,n,hd], truncated to tf32.
        const int bIdx = m0 >> 11;
        const int n0 = (m0 & 2047) + wy * 64;
        const int dg = d0 + wx * 32;
        const int which = dg / DIM;
        float* dstb = (which == 0) ? g_q : (which == 1) ? g_k : g_v;
#pragma unroll
        for (int ms = 0; ms < 4; ms++)
#pragma unroll
            for (int ns = 0; ns < 2; ns++) {
#pragma unroll
                for (int e = 0; e < acc[ms][ns].num_elements; e++)
                    acc[ms][ns].x[e] = wmma::__float_to_tf32(acc[ms][ns].x[e]);
                int dl = (dg % DIM) + ns * 16;
                int h = dl >> 6, hd = dl & 63;
                float* p = dstb + (((size_t)bIdx * NHEAD + h) * SEQ + n0 + ms * 16) * HDIM + hd;
                wmma::store_matrix_sync(p, acc[ms][ns], HDIM, wmma::mem_row_major);
            }
    } else {
        // Stage through smem, add bias, coalesced stores.
        float* Es = pool; // 128*68 = 8704 floats <= 11520
#pragma unroll
        for (int ms = 0; ms < 4; ms++)
#pragma unroll
            for (int ns = 0; ns < 2; ns++)
                wmma::store_matrix_sync(&Es[(wy * 64 + ms * 16) * 68 + wx * 32 + ns * 16],
                                        acc[ms][ns], 68, wmma::mem_row_major);
        __syncthreads();
#pragma unroll
        for (int i = 0; i < 16; i++) {
            int fi = tid + 128 * i;       // 0..2047 float4 slots
            int r = fi >> 4;
            int c4 = (fi & 15) << 2;
            float4 v = *(float4*)&Es[r * 68 + c4];
            float4 bv = *(const float4*)&bias[d0 + c4];
            v.x += bv.x; v.y += bv.y; v.z += bv.z; v.w += bv.w;
            *(float4*)&out[(size_t)(m0 + r) * DIM + d0 + c4] = v;
        }
    }
}

// ---------------------------------------------------------------------------
// Kernel 2: flash attention (tf32 wmma) over compacted keys.
// 128 query rows/block (256 thr, 8 warps), 32-row KV tiles, register-
// prefetched gathers. Output written tf32-truncated (fc consumes tf32).
// ---------------------------------------------------------------------------
__global__ __launch_bounds__(256) void attn_kernel()
{
    __shared__ float buf1[128 * 68];
    __shared__ float KVs[32 * 68];
    __shared__ float lsum[128];
    __shared__ float meanv[64];

    const int tid = threadIdx.x;
    const int warp = tid >> 5;
    const int bh = blockIdx.y;
    const int b = bh / NHEAD, h = bh % NHEAD;
    const int q0 = blockIdx.x * 128;
    const float* qb = g_q + (size_t)bh * SEQ * HDIM;
    const float* kb = g_k + (size_t)bh * SEQ * HDIM;
    const float* vb = g_v + (size_t)bh * SEQ * HDIM;
    const int cnt = g_cnt[b];
    const int* idxb = g_idx + b * SEQ;

    if (cnt == 0) {
        if (tid < 64) {
            float acc = 0.f;
            for (int k = 0; k < SEQ; k++) acc += vb[(size_t)k * HDIM + tid];
            meanv[tid] = wmma::__float_to_tf32(acc / (float)SEQ);
        }
        __syncthreads();
        int row = tid >> 1, half = tid & 1;
        float* dst = g_x + (size_t)(b * SEQ + q0 + row) * DIM + h * HDIM + half * 32;
#pragma unroll
        for (int c = 0; c < 32; c++) dst[c] = meanv[half * 32 + c];
        return;
    }

    const int lr = tid >> 4;
    const int gc4 = (tid & 15) << 2;

#pragma unroll
    for (int i = 0; i < 8; i++) {
        int r = lr + 16 * i;
        *(float4*)&buf1[r * 68 + gc4] = *(const float4*)&qb[(size_t)(q0 + r) * HDIM + gc4];
    }
    if (tid < 128) lsum[tid] = 0.f;
    __syncthreads();

    AFrag aq[8];
#pragma unroll
    for (int ks = 0; ks < 8; ks++)
        wmma::load_matrix_sync(aq[ks], &buf1[(warp * 16) * 68 + ks * 8], 68);

    CFrag ofrag[4];
#pragma unroll
    for (int dn = 0; dn < 4; dn++) wmma::fill_fragment(ofrag[dn], 0.f);

    const int ntiles = (cnt + 31) >> 5;

    int src[2];
    float4 kreg[2];
#pragma unroll
    for (int i = 0; i < 2; i++) {
        int r = lr + 16 * i;
        src[i] = (r < cnt) ? __ldg(&idxb[r]) : 0;
        kreg[i] = *(const float4*)&kb[(size_t)src[i] * HDIM + gc4];
    }

    for (int tile = 0; tile < ntiles; tile++) {
        const int k0 = tile << 5;
        __syncthreads();

#pragma unroll
        for (int i = 0; i < 2; i++)
            *(float4*)&KVs[(lr + 16 * i) * 68 + gc4] = kreg[i];
        __syncthreads();

        float4 vreg[2];
#pragma unroll
        for (int i = 0; i < 2; i++)
            vreg[i] = *(const float4*)&vb[(size_t)src[i] * HDIM + gc4];

        CFrag sfrag[2];
#pragma unroll
        for (int jn = 0; jn < 2; jn++) wmma::fill_fragment(sfrag[jn], 0.f);
#pragma unroll
        for (int ks = 0; ks < 8; ks++) {
#pragma unroll
            for (int jn = 0; jn < 2; jn++) {
                BFragCol bk;
                wmma::load_matrix_sync(bk, &KVs[(jn * 16) * 68 + ks * 8], 68);
                wmma::mma_sync(sfrag[jn], aq[ks], bk, sfrag[jn]);
            }
        }
#pragma unroll
        for (int jn = 0; jn < 2; jn++)
            wmma::store_matrix_sync(&buf1[(warp * 16) * 68 + jn * 16], sfrag[jn], 68,
                                    wmma::mem_row_major);
        __syncthreads();

        {
            const int row = tid >> 1, half = tid & 1;
            const int valid = cnt - k0;
            float* er = &buf1[row * 68 + half * 16];
            float ps = 0.f;
#pragma unroll
            for (int c4 = 0; c4 < 16; c4 += 4) {
                float4 v = *(float4*)&er[c4];
                int jb = half * 16 + c4;
                v.x = (jb + 0 < valid) ? __expf(v.x * SCALE) : 0.f;
                v.y = (jb + 1 < valid) ? __expf(v.y * SCALE) : 0.f;
                v.z = (jb + 2 < valid) ? __expf(v.z * SCALE) : 0.f;
                v.w = (jb + 3 < valid) ? __expf(v.w * SCALE) : 0.f;
                ps += v.x + v.y + v.z + v.w;
                *(float4*)&er[c4] = tf32x4(v);
            }
            ps += __shfl_xor_sync(0xffffffffu, ps, 1);
            if (half == 0) lsum[row] += ps;
        }

#pragma unroll
        for (int i = 0; i < 2; i++)
            *(float4*)&KVs[(lr + 16 * i) * 68 + gc4] = vreg[i];

        if (tile + 1 < ntiles) {
            const int kn = k0 + 32;
#pragma unroll
            for (int i = 0; i < 2; i++) {
                int g = kn + lr + 16 * i;
                src[i] = (g < cnt) ? __ldg(&idxb[g]) : 0;
                kreg[i] = *(const float4*)&kb[(size_t)src[i] * HDIM + gc4];
            }
        }
        __syncthreads();

#pragma unroll
        for (int js = 0; js < 4; js++) {
            AFrag ap;
            wmma::load_matrix_sync(ap, &buf1[(warp * 16) * 68 + js * 8], 68);
#pragma unroll
            for (int dn = 0; dn < 4; dn++) {
                BFragRow bv;
                wmma::load_matrix_sync(bv, &KVs[(js * 8) * 68 + dn * 16], 68);
                wmma::mma_sync(ofrag[dn], ap, bv, ofrag[dn]);
            }
        }
    }

    __syncthreads();
#pragma unroll
    for (int dn = 0; dn < 4; dn++)
        wmma::store_matrix_sync(&buf1[(warp * 16) * 68 + dn * 16], ofrag[dn], 68,
                                wmma::mem_row_major);
    __syncthreads();

    {
        const int row = tid >> 1, half = tid & 1;
        const float inv = 1.f / lsum[row];
        const float* srcp = &buf1[row * 68 + half * 32];
        float* dst = g_x + (size_t)(b * SEQ + q0 + row) * DIM + h * HDIM + half * 32;
#pragma unroll
        for (int c4 = 0; c4 < 32; c4 += 4) {
            float4 v = *(const float4*)&srcp[c4];
            v = make_float4(v.x * inv, v.y * inv, v.z * inv, v.w * inv);
            *(float4*)&dst[c4] = tf32x4(v);
        }
    }
}

// ---------------------------------------------------------------------------
// Launch
// ---------------------------------------------------------------------------
extern "C" void kernel_launch(void* const* d_in, const int* in_sizes, int n_in,
                              void* d_out, int out_size)
{
    const float* inputs = (const float*)d_in[0];
    const int*   pmask  = (const int*)d_in[1];
    const float* w_qkv  = (const float*)d_in[2];
    const float* w_fc   = (const float*)d_in[3];
    const float* b_fc   = (const float*)d_in[4];
    float* out = (float*)d_out;

    float* da;  cudaGetSymbolAddress((void**)&da, g_a);
    float* dwq; cudaGetSymbolAddress((void**)&dwq, g_wq);
    float* dwf; cudaGetSymbolAddress((void**)&dwf, g_wf);

    compact_kernel<<<BATCH, 256>>>(pmask);
    {
        int n4 = M_TOTAL * DIM / 4;
        convert_kernel<<<(n4 + 255) / 256, 256>>>(inputs, da, n4);
        n4 = QKV_DIM * DIM / 4;
        convert_kernel<<<(n4 + 255) / 256, 256>>>(w_qkv, dwq, n4);
        n4 = DIM * DIM / 4;
        convert_kernel<<<(n4 + 255) / 256, 256>>>(w_fc, dwf, n4);
    }
    {
        dim3 grid(QKV_DIM / 64, M_TOTAL / 128); // (36, 32) = 1152 CTAs
        tc_gemm_kernel<true><<<grid, 128>>>(nullptr, nullptr);
    }
    {
        dim3 grid(SEQ / 128, BATCH * NHEAD);    // (16, 24)
        attn_kernel<<<grid, 256>>>();
    }
    {
        dim3 grid(DIM / 64, M_TOTAL / 128);     // (12, 32) = 384 CTAs
        tc_gemm_kernel<false><<<grid, 128>>>(b_fc, out);
    }
}